// round 9
// baseline (speedup 1.0000x reference)
#include <cuda_runtime.h>
#include <cstdint>
#include <math.h>

// Problem constants
#define P     48
#define FLEN  168
#define HIST  336
#define HOFF  288    // HIST - P

__device__ __align__(16) float g_G[P * FLEN];   // G[k][t]
__device__ __align__(16) float g_C[FLEN];
__device__ float g_lv;

typedef unsigned long long ull;

__device__ __forceinline__ ull pack2(float a, float b) {
    ull r; asm("mov.b64 %0, {%1, %2};" : "=l"(r) : "f"(a), "f"(b)); return r;
}
__device__ __forceinline__ ull ffma2(ull a, ull b, ull c) {
    ull d; asm("fma.rn.f32x2 %0, %1, %2, %3;" : "=l"(d) : "l"(a), "l"(b), "l"(c)); return d;
}

// ---------------------------------------------------------------------------
// Kernel 1: precompute affine map (impulse response of the AR recurrence).
// Loop-carried dependency = ONE FFMA per step (lag-1 term last).
// ---------------------------------------------------------------------------
__global__ void precompute_kernel(const float* __restrict__ phi,
                                  const float* __restrict__ bias,
                                  const float* __restrict__ log_sigma2,
                                  const float* __restrict__ mu_p,
                                  const float* __restrict__ sigma_p) {
    __shared__ float h[P + 1][221];   // odd pitch -> conflict-free
    const int k = threadIdx.x;

    float ph[P];
#pragma unroll
    for (int j = 0; j < P; j++) ph[j] = phi[j];

    if (k <= P) {
#pragma unroll
        for (int i = 0; i < P; i++) h[k][i] = (k == i) ? 1.0f : 0.0f;  // k==P: zeros
        const float b0 = (k == P) ? bias[0] : 0.0f;

        float pw[8];                        // rolling window = h[k][t+40 .. t+47]
#pragma unroll
        for (int i = 0; i < 8; i++) pw[i] = h[k][40 + i];

#pragma unroll 1
        for (int t = 0; t < FLEN; t++) {
            float s0 = 0.f, s1 = 0.f, s2 = 0.f, s3 = 0.f;
#pragma unroll
            for (int j = 0; j < 40; j += 4) {           // smem terms, lag >= 9
                s0 += ph[j + 0] * h[k][t + j + 0];
                s1 += ph[j + 1] * h[k][t + j + 1];
                s2 += ph[j + 2] * h[k][t + j + 2];
                s3 += ph[j + 3] * h[k][t + j + 3];
            }
            float rest = b0 + ((s0 + s1) + (s2 + s3));
#pragma unroll
            for (int i = 0; i < 7; i++) rest += ph[40 + i] * pw[i];  // lag >= 2
            const float s = fmaf(ph[47], pw[7], rest);               // only lag-1 use
            h[k][P + t] = s;
#pragma unroll
            for (int i = 0; i < 7; i++) pw[i] = pw[i + 1];
            pw[7] = s;
        }
    }
    __syncthreads();

    const float mu = *mu_p;
    const float sg = *sigma_p;

    for (int t = threadIdx.x; t < FLEN; t += blockDim.x) {
        float sum = 0.0f;
        for (int kk = 0; kk < P; kk++) sum += h[kk][P + t];
        g_C[t] = mu + sg * h[P][P + t] - mu * sum;
    }
    for (int idx = threadIdx.x; idx < P * FLEN; idx += blockDim.x) {
        const int kk = idx / FLEN;
        const int t  = idx - kk * FLEN;
        g_G[idx] = h[kk][P + t];
    }
    if (threadIdx.x == 0) g_lv = log_sigma2[0] + 2.0f * logf(sg);
}

// ---------------------------------------------------------------------------
// Kernel 2: 128 rows x 168 t per CTA, 448 threads = 32 row-lanes x 14 t-warps
// (14 x 12 = 168: FULL t coverage — round 8's bug was 7 warps covering 84).
// 4 rows x 12 t per thread. G/C via uniform 16B LDG (L1-hot, 1 wavefront).
// Y staged once; phased coalesced epilogue through aliased smem restage.
// ---------------------------------------------------------------------------
#define TPB 448
#define YPITCH 132

__global__ void __launch_bounds__(TPB, 2)
forecast_kernel(const float* __restrict__ enc_l, float* __restrict__ out, int B) {
    __shared__ __align__(16) char smem_buf[64 * 85 * 8];   // 43520 B
    float* Ys = (float*)smem_buf;     // [48][132] mainloop (25344 B)
    ull*   Co = (ull*)smem_buf;       // [64][85]  epilogue restage (aliases Ys)

    const int brow0 = blockIdx.x * 128;

    // --- Stage Y transposed + row-permuted: row r -> slot 4*(r&31)+(r>>5),
    // so lane tr's LDS.128 yields rows {tr, tr+32, tr+64, tr+96}. ---
    for (int i = threadIdx.x; i < 128 * (P / 4); i += TPB) {
        const int r  = i / (P / 4);
        const int j4 = i - r * (P / 4);
        const int gr = brow0 + r;
        float4 v = (gr < B)
            ? *(const float4*)(enc_l + (size_t)gr * HIST + HOFF + j4 * 4)
            : make_float4(0.f, 0.f, 0.f, 0.f);
        const int slot = 4 * (r & 31) + (r >> 5);
        Ys[(4 * j4 + 0) * YPITCH + slot] = v.x;
        Ys[(4 * j4 + 1) * YPITCH + slot] = v.y;
        Ys[(4 * j4 + 2) * YPITCH + slot] = v.z;
        Ys[(4 * j4 + 3) * YPITCH + slot] = v.w;
    }
    __syncthreads();

    const int tr = threadIdx.x & 31;   // lane: rows tr + 32*ri
    const int tc = threadIdx.x >> 5;   // warp 0..13: t = tc*12 .. +11
    const int t0 = tc * 12;

    // acc init from C (uniform 16B LDG)
    ull acc[4][6];
    {
        const ulonglong2* cp = (const ulonglong2*)(g_C + t0);   // 48*tc B: 16B-aligned
        const ulonglong2 ca = cp[0], cb = cp[1], cc = cp[2];
#pragma unroll
        for (int ri = 0; ri < 4; ri++) {
            acc[ri][0] = ca.x; acc[ri][1] = ca.y;
            acc[ri][2] = cb.x; acc[ri][3] = cb.y;
            acc[ri][4] = cc.x; acc[ri][5] = cc.y;
        }
    }

    const float* ya = Ys + 4 * tr;
    const ulonglong2* gb = (const ulonglong2*)g_G + 3 * tc;   // G[k][t0..] = gb[42k..]

#pragma unroll 4
    for (int k = 0; k < P; ++k) {
        const float4 av = *(const float4*)(ya + k * YPITCH);   // 4 rows' y[k]
        const ulonglong2* gp = gb + k * 42;                    // uniform LDG.128

        const ull y0 = pack2(av.x, av.x);
        const ull y1 = pack2(av.y, av.y);
        const ull y2 = pack2(av.z, av.z);
        const ull y3 = pack2(av.w, av.w);

        ulonglong2 g = gp[0];
        acc[0][0] = ffma2(g.x, y0, acc[0][0]); acc[0][1] = ffma2(g.y, y0, acc[0][1]);
        acc[1][0] = ffma2(g.x, y1, acc[1][0]); acc[1][1] = ffma2(g.y, y1, acc[1][1]);
        acc[2][0] = ffma2(g.x, y2, acc[2][0]); acc[2][1] = ffma2(g.y, y2, acc[2][1]);
        acc[3][0] = ffma2(g.x, y3, acc[3][0]); acc[3][1] = ffma2(g.y, y3, acc[3][1]);
        g = gp[1];
        acc[0][2] = ffma2(g.x, y0, acc[0][2]); acc[0][3] = ffma2(g.y, y0, acc[0][3]);
        acc[1][2] = ffma2(g.x, y1, acc[1][2]); acc[1][3] = ffma2(g.y, y1, acc[1][3]);
        acc[2][2] = ffma2(g.x, y2, acc[2][2]); acc[2][3] = ffma2(g.y, y2, acc[2][3]);
        acc[3][2] = ffma2(g.x, y3, acc[3][2]); acc[3][3] = ffma2(g.y, y3, acc[3][3]);
        g = gp[2];
        acc[0][4] = ffma2(g.x, y0, acc[0][4]); acc[0][5] = ffma2(g.y, y0, acc[0][5]);
        acc[1][4] = ffma2(g.x, y1, acc[1][4]); acc[1][5] = ffma2(g.y, y1, acc[1][5]);
        acc[2][4] = ffma2(g.x, y2, acc[2][4]); acc[2][5] = ffma2(g.y, y2, acc[2][5]);
        acc[3][4] = ffma2(g.x, y3, acc[3][4]); acc[3][5] = ffma2(g.y, y3, acc[3][5]);
    }

    // --- Epilogue: 2 phases of 64 rows through smem restage (aliases Ys) ---
#pragma unroll
    for (int p = 0; p < 2; ++p) {
        __syncthreads();    // p0: Ys reads done; p1: p0's Co reads done
        ull* c0 = Co + tr * 85 + tc * 6;          // acc[2p]   -> local row tr+64p
        ull* c1 = Co + (tr + 32) * 85 + tc * 6;   // acc[2p+1] -> local row tr+32+64p
#pragma unroll
        for (int j = 0; j < 6; j++) { c0[j] = acc[2 * p][j]; c1[j] = acc[2 * p + 1][j]; }
        __syncthreads();
        for (int i = threadIdx.x; i < 64 * (FLEN / 2); i += TPB) {
            const int r = i / (FLEN / 2);
            const int c = i - r * (FLEN / 2);
            const int gr = brow0 + 64 * p + r;
            if (gr < B)
                ((ull*)(out + (size_t)gr * FLEN))[c] = Co[r * 85 + c];
        }
    }

    // --- logvar half: constant, coalesced float4 ---
    const float lv = g_lv;
    const float4 lv4 = make_float4(lv, lv, lv, lv);
    const size_t lvbase = (size_t)B * FLEN;
#pragma unroll 2
    for (int i = threadIdx.x; i < 128 * (FLEN / 4); i += TPB) {
        const int r = i / (FLEN / 4);
        const int c = i - r * (FLEN / 4);
        const int gr = brow0 + r;
        if (gr < B)
            *(float4*)(out + lvbase + (size_t)gr * FLEN + 4 * c) = lv4;
    }
}

// ---------------------------------------------------------------------------
extern "C" void kernel_launch(void* const* d_in, const int* in_sizes, int n_in,
                              void* d_out, int out_size) {
    const float* enc_l      = (const float*)d_in[0];
    const float* phi        = (const float*)d_in[4];
    const float* bias       = (const float*)d_in[5];
    const float* log_sigma2 = (const float*)d_in[6];
    const float* mu         = (const float*)d_in[7];
    const float* sigma      = (const float*)d_in[8];

    const int B = in_sizes[0] / HIST;

    precompute_kernel<<<1, 64>>>(phi, bias, log_sigma2, mu, sigma);

    const int nblk = (B + 127) / 128;
    forecast_kernel<<<nblk, TPB>>>(enc_l, (float*)d_out, B);
}

// round 11
// speedup vs baseline: 1.6906x; 1.6906x over previous
#include <cuda_runtime.h>
#include <cuda_bf16.h>
#include <cstdint>
#include <math.h>

#define P     48
#define FLEN  168
#define HIST  336
#define HOFF  288
#define NCT   21      // col-tiles of 8
#define NKS   9       // k-steps of 16 (K = 144 = hi(48) + hi(48) -> wait: [Yh|Yl|Yh])

// Precomputed: B operand packed in m16n8k16 b-fragment register order, C, lv
__device__ __align__(16) uint32_t g_Bfrag[NCT * NKS * 32 * 2];
__device__ __align__(16) float g_C[FLEN];
__device__ float g_lv;

typedef unsigned long long ull;

// ---------------------------------------------------------------------------
// Kernel 1: precompute. AR impulse response -> G; emit C, lv, and G as
// bf16-split b-fragments: zones kk<48:Gh, 48..95:Gh, 96..143:Gl (pairs with
// A zones [Yh|Yl|Yh] to realize Yh*Gh + Yl*Gh + Yh*Gl ~= fp32 Y*G).
// ---------------------------------------------------------------------------
__global__ void precompute_kernel(const float* __restrict__ phi,
                                  const float* __restrict__ bias,
                                  const float* __restrict__ log_sigma2,
                                  const float* __restrict__ mu_p,
                                  const float* __restrict__ sigma_p) {
    __shared__ float h[P + 1][221];
    const int k = threadIdx.x;

    float ph[P];
#pragma unroll
    for (int j = 0; j < P; j++) ph[j] = phi[j];

    if (k <= P) {
#pragma unroll
        for (int i = 0; i < P; i++) h[k][i] = (k == i) ? 1.0f : 0.0f;
        const float b0 = (k == P) ? bias[0] : 0.0f;
        float pw[8];
#pragma unroll
        for (int i = 0; i < 8; i++) pw[i] = h[k][40 + i];
#pragma unroll 1
        for (int t = 0; t < FLEN; t++) {
            float s0 = 0.f, s1 = 0.f, s2 = 0.f, s3 = 0.f;
#pragma unroll
            for (int j = 0; j < 40; j += 4) {
                s0 += ph[j + 0] * h[k][t + j + 0];
                s1 += ph[j + 1] * h[k][t + j + 1];
                s2 += ph[j + 2] * h[k][t + j + 2];
                s3 += ph[j + 3] * h[k][t + j + 3];
            }
            float rest = b0 + ((s0 + s1) + (s2 + s3));
#pragma unroll
            for (int i = 0; i < 7; i++) rest += ph[40 + i] * pw[i];
            const float s = fmaf(ph[47], pw[7], rest);
            h[k][P + t] = s;
#pragma unroll
            for (int i = 0; i < 7; i++) pw[i] = pw[i + 1];
            pw[7] = s;
        }
    }
    __syncthreads();

    const float mu = *mu_p;
    const float sg = *sigma_p;

    for (int t = threadIdx.x; t < FLEN; t += blockDim.x) {
        float sum = 0.0f;
        for (int kk = 0; kk < P; kk++) sum += h[kk][P + t];
        g_C[t] = mu + sg * h[P][P + t] - mu * sum;
    }
    if (threadIdx.x == 0) g_lv = log_sigma2[0] + 2.0f * logf(sg);

    // b-fragments: for mma.m16n8k16 row.col, lane L reg r holds
    // { B[kk][n], B[kk+1][n] } with n = L>>2, kk = ks*16 + (L&3)*2 + r*8.
    for (int idx = threadIdx.x; idx < NCT * NKS * 32 * 2; idx += blockDim.x) {
        const int reg  = idx & 1;
        const int lane = (idx >> 1) & 31;
        const int ks   = (idx >> 6) % NKS;
        const int ct   = (idx >> 6) / NKS;
        const int n    = ct * 8 + (lane >> 2);
        const int kk0  = ks * 16 + (lane & 3) * 2 + reg * 8;

        unsigned short e[2];
#pragma unroll
        for (int q = 0; q < 2; q++) {
            const int kk = kk0 + q;
            const float g = h[kk % P][P + n];
            const __nv_bfloat16 bh = __float2bfloat16(g);
            e[q] = (kk < 96)
                 ? __bfloat16_as_ushort(bh)
                 : __bfloat16_as_ushort(__float2bfloat16(g - __bfloat162float(bh)));
        }
        g_Bfrag[((ct * NKS + ks) * 32 + lane) * 2 + reg] =
            (uint32_t)e[0] | ((uint32_t)e[1] << 16);
    }
}

// ---------------------------------------------------------------------------
// Kernel 2: HMMA forecast. 256 threads, 128 rows/CTA; warp w owns rows
// [16w,16w+16) x all 168 cols (21 col-tiles, acc = 84 fp32 regs).
// A zones [Yh|Yl|Yh] staged row-major bf16 in smem (pitch 152 -> all a-frag
// LDS.32 conflict-free); B fragments staged linearly, LDS.64 conflict-free.
// ---------------------------------------------------------------------------
#define TPB 256
#define YP  152                       // Y row pitch in bf16 (76 words)
#define YS_BYTES (128 * YP * 2)       // 38912
#define BF_OFF   YS_BYTES             // 48384 bytes of b-frags
#define CS_OFF   (BF_OFF + NCT * NKS * 32 * 2 * 4)   // 87296
#define SMEM_DYN (CS_OFF + FLEN * 4)                 // 87968

__global__ void __launch_bounds__(TPB, 2)
forecast_mma(const float* __restrict__ enc_l, float* __restrict__ out, int B) {
    extern __shared__ __align__(16) char dsm[];
    __nv_bfloat16* Ys = (__nv_bfloat16*)dsm;        // [128][YP]
    uint32_t* Bf = (uint32_t*)(dsm + BF_OFF);
    float*    Cs = (float*)(dsm + CS_OFF);

    const int tid = threadIdx.x;
    const int brow0 = blockIdx.x * 128;

    // --- stage b-fragments (linear, coalesced) + C ---
    for (int i = tid; i < (NCT * NKS * 32 * 2) / 4; i += TPB)
        ((int4*)Bf)[i] = ((const int4*)g_Bfrag)[i];
    for (int i = tid; i < FLEN; i += TPB) Cs[i] = g_C[i];

    // --- stage Y: thread t -> row t>>1, k-half (t&1)*24; zones [Yh|Yl|Yh] ---
    {
        const int row = tid >> 1;
        const int hh  = (tid & 1) * 24;
        const int gr  = (brow0 + row < B) ? (brow0 + row) : (B - 1);
        const float4* yp = (const float4*)(enc_l + (size_t)gr * HIST + HOFF + hh);
        uint32_t* yr = (uint32_t*)(Ys + row * YP);
#pragma unroll
        for (int q = 0; q < 6; q++) {
            const float4 v = yp[q];
            const unsigned short hx = __bfloat16_as_ushort(__float2bfloat16(v.x));
            const unsigned short hy = __bfloat16_as_ushort(__float2bfloat16(v.y));
            const unsigned short hz = __bfloat16_as_ushort(__float2bfloat16(v.z));
            const unsigned short hw = __bfloat16_as_ushort(__float2bfloat16(v.w));
            const uint32_t h0 = (uint32_t)hx | ((uint32_t)hy << 16);
            const uint32_t h1 = (uint32_t)hz | ((uint32_t)hw << 16);
            const unsigned short lx = __bfloat16_as_ushort(
                __float2bfloat16(v.x - __bfloat162float(__ushort_as_bfloat16(hx))));
            const unsigned short ly = __bfloat16_as_ushort(
                __float2bfloat16(v.y - __bfloat162float(__ushort_as_bfloat16(hy))));
            const unsigned short lz = __bfloat16_as_ushort(
                __float2bfloat16(v.z - __bfloat162float(__ushort_as_bfloat16(hz))));
            const unsigned short lw = __bfloat16_as_ushort(
                __float2bfloat16(v.w - __bfloat162float(__ushort_as_bfloat16(hw))));
            const uint32_t l0 = (uint32_t)lx | ((uint32_t)ly << 16);
            const uint32_t l1 = (uint32_t)lz | ((uint32_t)lw << 16);
            const int c = (hh >> 1) + 2 * q;      // u32 col within zone
            yr[c]          = h0; yr[c + 1]      = h1;   // zone0: Yh  (k 0..47)
            yr[c + 24]     = l0; yr[c + 25]     = l1;   // zone1: Yl  (k 48..95)
            yr[c + 48]     = h0; yr[c + 49]     = h1;   // zone2: Yh  (k 96..143)
        }
    }
    __syncthreads();

    const int w    = tid >> 5;
    const int lane = tid & 31;
    const int gr8  = lane >> 2;        // 0..7
    const int cl   = lane & 3;
    const int r0   = w * 16 + gr8;     // local rows r0, r0+8

    // acc[ct][4], init from C (same C for both row groups)
    float acc[NCT][4];
#pragma unroll
    for (int ct = 0; ct < NCT; ct++) {
        const float c0 = Cs[ct * 8 + 2 * cl];
        const float c1 = Cs[ct * 8 + 2 * cl + 1];
        acc[ct][0] = c0; acc[ct][1] = c1; acc[ct][2] = c0; acc[ct][3] = c1;
    }

    const uint32_t* y0 = (const uint32_t*)(Ys + r0 * YP) + cl;        // +ks*8
    const uint32_t* y1 = (const uint32_t*)(Ys + (r0 + 8) * YP) + cl;
    const ull* bbase = (const ull*)Bf + lane;                          // +(ct*9+ks)*32

#pragma unroll 1
    for (int ks = 0; ks < NKS; ks++) {
        const uint32_t a0 = y0[ks * 8];          // A[r0][ck..ck+1]
        const uint32_t a1 = y1[ks * 8];          // A[r0+8][ck..]
        const uint32_t a2 = y0[ks * 8 + 4];      // A[r0][ck+8..]
        const uint32_t a3 = y1[ks * 8 + 4];
        const ull* bp = bbase + ks * 32;
#pragma unroll
        for (int ct = 0; ct < NCT; ct++) {
            const ull bb = bp[ct * (NKS * 32)];
            const uint32_t b0 = (uint32_t)bb;
            const uint32_t b1 = (uint32_t)(bb >> 32);
            asm volatile(
                "mma.sync.aligned.m16n8k16.row.col.f32.bf16.bf16.f32 "
                "{%0,%1,%2,%3}, {%4,%5,%6,%7}, {%8,%9}, {%0,%1,%2,%3};"
                : "+f"(acc[ct][0]), "+f"(acc[ct][1]),
                  "+f"(acc[ct][2]), "+f"(acc[ct][3])
                : "r"(a0), "r"(a1), "r"(a2), "r"(a3), "r"(b0), "r"(b1));
        }
    }

    // --- Epilogue: direct 8B stores per c-frag pair ---
    const int grow0 = brow0 + r0;
    const int grow1 = grow0 + 8;
    float* o0 = out + (size_t)grow0 * FLEN + 2 * cl;
    float* o1 = out + (size_t)grow1 * FLEN + 2 * cl;
    const bool ok0 = grow0 < B, ok1 = grow1 < B;
#pragma unroll
    for (int ct = 0; ct < NCT; ct++) {
        if (ok0) *(float2*)(o0 + ct * 8) = make_float2(acc[ct][0], acc[ct][1]);
        if (ok1) *(float2*)(o1 + ct * 8) = make_float2(acc[ct][2], acc[ct][3]);
    }

    // --- logvar half: constant, coalesced float4 ---
    const float lv = g_lv;
    const float4 lv4 = make_float4(lv, lv, lv, lv);
    const size_t lvbase = (size_t)B * FLEN;
#pragma unroll 2
    for (int i = tid; i < 128 * (FLEN / 4); i += TPB) {
        const int r = i / (FLEN / 4);
        const int c = i - r * (FLEN / 4);
        const int gr = brow0 + r;
        if (gr < B)
            *(float4*)(out + lvbase + (size_t)gr * FLEN + 4 * c) = lv4;
    }
}

// ---------------------------------------------------------------------------
extern "C" void kernel_launch(void* const* d_in, const int* in_sizes, int n_in,
                              void* d_out, int out_size) {
    const float* enc_l      = (const float*)d_in[0];
    const float* phi        = (const float*)d_in[4];
    const float* bias       = (const float*)d_in[5];
    const float* log_sigma2 = (const float*)d_in[6];
    const float* mu         = (const float*)d_in[7];
    const float* sigma      = (const float*)d_in[8];

    const int B = in_sizes[0] / HIST;

    static int smem_set = 0;
    if (!smem_set) {
        cudaFuncSetAttribute(forecast_mma,
                             cudaFuncAttributeMaxDynamicSharedMemorySize, SMEM_DYN);
        smem_set = 1;
    }

    precompute_kernel<<<1, 64>>>(phi, bias, log_sigma2, mu, sigma);

    const int nblk = (B + 127) / 128;
    forecast_mma<<<nblk, TPB, SMEM_DYN>>>(enc_l, (float*)d_out, B);
}

// round 12
// speedup vs baseline: 2.0940x; 1.2386x over previous
#include <cuda_runtime.h>
#include <cuda_bf16.h>
#include <cstdint>
#include <math.h>

#define P     48
#define FLEN  168
#define HIST  336
#define HOFF  288
#define NCT   21      // col-tiles of 8
#define NBS   6       // stored b-frag k-steps: 0..2 = Gh chunks, 3..5 = Gl chunks

// Precomputed: B operand packed in m16n8k16 b-fragment order (deduped), C, lv
__device__ __align__(16) uint32_t g_Bfrag[NCT * NBS * 32 * 2];   // 32256 B
__device__ __align__(16) float g_C[FLEN];
__device__ float g_lv;

typedef unsigned long long ull;

// ---------------------------------------------------------------------------
// Kernel 1: precompute (512 threads).
// Stage A: 48 sequential AR steps (impulse response columns, 49 threads).
// Stage B: log-step composition — for t >= 48:
//   h[k][P+t] = sum_m h[m][P+t-48] * h[k][P+m]   (+ h[P][P+t-48] for k==P)
// done in 3 parallel 48x49x48 stages. Then emit C, lv, deduped b-frags.
// ---------------------------------------------------------------------------
__global__ void precompute_kernel(const float* __restrict__ phi,
                                  const float* __restrict__ bias,
                                  const float* __restrict__ log_sigma2,
                                  const float* __restrict__ mu_p,
                                  const float* __restrict__ sigma_p) {
    __shared__ float h[P + 1][221];
    const int tid = threadIdx.x;

    // --- Stage A: base 48 steps ---
    if (tid <= P) {
        const int k = tid;
        float ph[P];
#pragma unroll
        for (int j = 0; j < P; j++) ph[j] = phi[j];
#pragma unroll
        for (int i = 0; i < P; i++) h[k][i] = (k == i) ? 1.0f : 0.0f;
        const float b0 = (k == P) ? bias[0] : 0.0f;
        float pw[8];
#pragma unroll
        for (int i = 0; i < 8; i++) pw[i] = h[k][40 + i];
#pragma unroll 1
        for (int t = 0; t < P; t++) {
            float s0 = 0.f, s1 = 0.f, s2 = 0.f, s3 = 0.f;
#pragma unroll
            for (int j = 0; j < 40; j += 4) {
                s0 += ph[j + 0] * h[k][t + j + 0];
                s1 += ph[j + 1] * h[k][t + j + 1];
                s2 += ph[j + 2] * h[k][t + j + 2];
                s3 += ph[j + 3] * h[k][t + j + 3];
            }
            float rest = b0 + ((s0 + s1) + (s2 + s3));
#pragma unroll
            for (int i = 0; i < 7; i++) rest += ph[40 + i] * pw[i];
            const float s = fmaf(ph[47], pw[7], rest);
            h[k][P + t] = s;
#pragma unroll
            for (int i = 0; i < 7; i++) pw[i] = pw[i + 1];
            pw[7] = s;
        }
    }
    __syncthreads();

    // --- Stage B: 3 composition stages (t in [48,96), [96,144), [144,168)) ---
#pragma unroll 1
    for (int st = 1; st <= 3; st++) {
        const int tbase = 48 * st;
        const int cnt   = (st < 3) ? 48 : (FLEN - 144);     // 48,48,24
        const int total = cnt * (P + 1);
        for (int idx = tid; idx < total; idx += blockDim.x) {
            const int tl = idx / (P + 1);
            const int k  = idx - tl * (P + 1);
            const int t  = tbase + tl;
            float s = (k == P) ? h[P][P + t - 48] : 0.0f;
            float a0 = 0.f, a1 = 0.f, a2 = 0.f, a3 = 0.f;
#pragma unroll
            for (int m = 0; m < P; m += 4) {
                a0 += h[m + 0][P + t - 48] * h[k][P + m + 0];
                a1 += h[m + 1][P + t - 48] * h[k][P + m + 1];
                a2 += h[m + 2][P + t - 48] * h[k][P + m + 2];
                a3 += h[m + 3][P + t - 48] * h[k][P + m + 3];
            }
            h[k][P + t] = s + ((a0 + a1) + (a2 + a3));
        }
        __syncthreads();
    }

    const float mu = *mu_p;
    const float sg = *sigma_p;

    for (int t = tid; t < FLEN; t += blockDim.x) {
        float sum = 0.0f;
        for (int kk = 0; kk < P; kk++) sum += h[kk][P + t];
        g_C[t] = mu + sg * h[P][P + t] - mu * sum;
    }
    if (tid == 0) g_lv = log_sigma2[0] + 2.0f * logf(sg);

    // deduped b-frags: cs<3 -> Gh chunk cs; cs>=3 -> Gl chunk cs-3.
    // lane L reg r holds {B[k][n], B[k+1][n]}, n = ct*8 + L>>2,
    // k = (cs%3)*16 + (L&3)*2 + r*8.
    for (int idx = tid; idx < NCT * NBS * 32 * 2; idx += blockDim.x) {
        const int reg  = idx & 1;
        const int lane = (idx >> 1) & 31;
        const int cs   = (idx >> 6) % NBS;
        const int ct   = (idx >> 6) / NBS;
        const int n    = ct * 8 + (lane >> 2);
        const int k0   = (cs % 3) * 16 + (lane & 3) * 2 + reg * 8;
        unsigned short e[2];
#pragma unroll
        for (int q = 0; q < 2; q++) {
            const float g = h[k0 + q][P + n];
            const __nv_bfloat16 bh = __float2bfloat16(g);
            e[q] = (cs < 3)
                 ? __bfloat16_as_ushort(bh)
                 : __bfloat16_as_ushort(__float2bfloat16(g - __bfloat162float(bh)));
        }
        g_Bfrag[((ct * NBS + cs) * 32 + lane) * 2 + reg] =
            (uint32_t)e[0] | ((uint32_t)e[1] << 16);
    }
}

// ---------------------------------------------------------------------------
// Kernel 2: HMMA forecast. 256 threads, 64 rows/CTA; warp w: row-group
// w>>2... w>>1 (16 rows) x col-half (11 or 10 col-tiles). acc = 44 regs max.
// Ys stores hi|lo zones only (pitch 208B -> a-frag LDS.32 hits all 32 banks).
// ---------------------------------------------------------------------------
#define TPB   256
#define YPU   52      // Ys row pitch in u32 (208 B)
#define YS_BYTES (64 * YPU * 4)                      // 13312
#define BF_OFF   YS_BYTES
#define CS_OFF   (BF_OFF + NCT * NBS * 32 * 2 * 4)   // 45568
#define SMEM_DYN (CS_OFF + FLEN * 4)                 // 46240

template <int NT>
__device__ __forceinline__ void warp_tile(
    const uint32_t* __restrict__ yu0, const uint32_t* __restrict__ yu1,
    const ull* __restrict__ bbase, const float* __restrict__ Cs,
    float* __restrict__ out, int ctb, int cl, int grow0, int grow1, int B) {

    float acc[NT][4];
#pragma unroll
    for (int ct = 0; ct < NT; ct++) {
        const float c0 = Cs[(ctb + ct) * 8 + 2 * cl];
        const float c1 = Cs[(ctb + ct) * 8 + 2 * cl + 1];
        acc[ct][0] = c0; acc[ct][1] = c1; acc[ct][2] = c0; acc[ct][3] = c1;
    }

#pragma unroll
    for (int ks = 0; ks < 9; ks++) {
        const int zone  = (ks >= 3 && ks < 6) ? 1 : 0;
        const int chunk = ks % 3;
        const int bsel  = (ks < 3) ? ks : ks - 3;
        const int aoff  = zone * 24 + chunk * 8;
        const uint32_t a0 = yu0[aoff],     a1 = yu1[aoff];
        const uint32_t a2 = yu0[aoff + 4], a3 = yu1[aoff + 4];
        const ull* bp = bbase + bsel * 32;
#pragma unroll
        for (int ct = 0; ct < NT; ct++) {
            const ull bb = bp[ct * (NBS * 32)];
            const uint32_t b0 = (uint32_t)bb;
            const uint32_t b1 = (uint32_t)(bb >> 32);
            asm volatile(
                "mma.sync.aligned.m16n8k16.row.col.f32.bf16.bf16.f32 "
                "{%0,%1,%2,%3}, {%4,%5,%6,%7}, {%8,%9}, {%0,%1,%2,%3};"
                : "+f"(acc[ct][0]), "+f"(acc[ct][1]),
                  "+f"(acc[ct][2]), "+f"(acc[ct][3])
                : "r"(a0), "r"(a1), "r"(a2), "r"(a3), "r"(b0), "r"(b1));
        }
    }

    float* o0 = out + (size_t)grow0 * FLEN + ctb * 8 + 2 * cl;
    float* o1 = out + (size_t)grow1 * FLEN + ctb * 8 + 2 * cl;
    const bool ok0 = grow0 < B, ok1 = grow1 < B;
#pragma unroll
    for (int ct = 0; ct < NT; ct++) {
        if (ok0) *(float2*)(o0 + ct * 8) = make_float2(acc[ct][0], acc[ct][1]);
        if (ok1) *(float2*)(o1 + ct * 8) = make_float2(acc[ct][2], acc[ct][3]);
    }
}

__global__ void __launch_bounds__(TPB, 3)
forecast_mma(const float* __restrict__ enc_l, float* __restrict__ out, int B) {
    extern __shared__ __align__(16) char dsm[];
    uint32_t* Ys = (uint32_t*)dsm;                 // [64][YPU]: hi u32 0..23, lo 24..47
    uint32_t* Bf = (uint32_t*)(dsm + BF_OFF);
    float*    Cs = (float*)(dsm + CS_OFF);

    const int tid = threadIdx.x;
    const int brow0 = blockIdx.x * 64;

    // --- stage b-frags (linear) + C ---
    for (int i = tid; i < (NCT * NBS * 32 * 2) / 4; i += TPB)
        ((int4*)Bf)[i] = ((const int4*)g_Bfrag)[i];
    for (int i = tid; i < FLEN; i += TPB) Cs[i] = g_C[i];

    // --- stage Y: thread -> (row = tid>>2, quarter q = tid&3 covers k 12q..12q+11) ---
    {
        const int row = tid >> 2;
        const int q   = tid & 3;
        const int gr  = (brow0 + row < B) ? (brow0 + row) : (B - 1);
        const float4* yp = (const float4*)(enc_l + (size_t)gr * HIST + HOFF + 12 * q);
        uint32_t* yr = Ys + row * YPU;
#pragma unroll
        for (int j = 0; j < 3; j++) {
            const float4 v = yp[j];
            const unsigned short hx = __bfloat16_as_ushort(__float2bfloat16(v.x));
            const unsigned short hy = __bfloat16_as_ushort(__float2bfloat16(v.y));
            const unsigned short hz = __bfloat16_as_ushort(__float2bfloat16(v.z));
            const unsigned short hw = __bfloat16_as_ushort(__float2bfloat16(v.w));
            const unsigned short lx = __bfloat16_as_ushort(
                __float2bfloat16(v.x - __bfloat162float(__ushort_as_bfloat16(hx))));
            const unsigned short ly = __bfloat16_as_ushort(
                __float2bfloat16(v.y - __bfloat162float(__ushort_as_bfloat16(hy))));
            const unsigned short lz = __bfloat16_as_ushort(
                __float2bfloat16(v.z - __bfloat162float(__ushort_as_bfloat16(hz))));
            const unsigned short lw = __bfloat16_as_ushort(
                __float2bfloat16(v.w - __bfloat162float(__ushort_as_bfloat16(hw))));
            const int c = 6 * q + 2 * j;
            yr[c]          = (uint32_t)hx | ((uint32_t)hy << 16);
            yr[c + 1]      = (uint32_t)hz | ((uint32_t)hw << 16);
            yr[24 + c]     = (uint32_t)lx | ((uint32_t)ly << 16);
            yr[24 + c + 1] = (uint32_t)lz | ((uint32_t)lw << 16);
        }
    }
    __syncthreads();

    const int w    = tid >> 5;
    const int lane = tid & 31;
    const int rg   = w >> 1;          // row-group: rows rg*16 ..
    const int half = w & 1;           // col-half: ct 0..10 or 11..20
    const int gr8  = lane >> 2;
    const int cl   = lane & 3;
    const int r0   = rg * 16 + gr8;

    const uint32_t* yu0 = Ys + r0 * YPU + cl;
    const uint32_t* yu1 = yu0 + 8 * YPU;
    const int ctb = half ? 11 : 0;
    const ull* bbase = (const ull*)Bf + ctb * (NBS * 32) + lane;

    const int grow0 = brow0 + r0;
    const int grow1 = grow0 + 8;

    if (half == 0)
        warp_tile<11>(yu0, yu1, bbase, Cs, out, ctb, cl, grow0, grow1, B);
    else
        warp_tile<10>(yu0, yu1, bbase, Cs, out, ctb, cl, grow0, grow1, B);

    // --- logvar half: constant, coalesced float4 ---
    const float lv = g_lv;
    const float4 lv4 = make_float4(lv, lv, lv, lv);
    const size_t lvbase = (size_t)B * FLEN;
#pragma unroll 2
    for (int i = tid; i < 64 * (FLEN / 4); i += TPB) {
        const int r = i / (FLEN / 4);
        const int c = i - r * (FLEN / 4);
        const int gr = brow0 + r;
        if (gr < B)
            *(float4*)(out + lvbase + (size_t)gr * FLEN + 4 * c) = lv4;
    }
}

// ---------------------------------------------------------------------------
extern "C" void kernel_launch(void* const* d_in, const int* in_sizes, int n_in,
                              void* d_out, int out_size) {
    const float* enc_l      = (const float*)d_in[0];
    const float* phi        = (const float*)d_in[4];
    const float* bias       = (const float*)d_in[5];
    const float* log_sigma2 = (const float*)d_in[6];
    const float* mu         = (const float*)d_in[7];
    const float* sigma      = (const float*)d_in[8];

    const int B = in_sizes[0] / HIST;

    static int smem_set = 0;
    if (!smem_set) {
        cudaFuncSetAttribute(forecast_mma,
                             cudaFuncAttributeMaxDynamicSharedMemorySize, SMEM_DYN);
        smem_set = 1;
    }

    precompute_kernel<<<1, 512>>>(phi, bias, log_sigma2, mu, sigma);

    const int nblk = (B + 63) / 64;
    forecast_mma<<<nblk, TPB, SMEM_DYN>>>(enc_l, (float*)d_out, B);
}